// round 1
// baseline (speedup 1.0000x reference)
#include <cuda_runtime.h>

// Problem constants
#define BATCH 4
#define SEQ   2048
#define CIN   1024
#define C3    3072
#define NH    8
#define DH    128
#define SCALE_F 0.08838834764831845f   // 1/sqrt(128)

// Scratch (device globals — no runtime allocation)
__device__ float g_qkv[(size_t)BATCH * C3 * SEQ];    // (B, 3072, S)  96 MB
__device__ float g_M[(size_t)BATCH * NH * DH * DH];  // (B, H, 128, 128)  2 MB
__device__ float g_C[(size_t)BATCH * CIN * SEQ];     // (B, 1024, S)  32 MB

// ---------------------------------------------------------------------------
// zero M (needed because VK^T uses split-K atomics)
// ---------------------------------------------------------------------------
__global__ void zero_M_kernel() {
    int i = blockIdx.x * blockDim.x + threadIdx.x;
    if (i < BATCH * NH * DH * DH) g_M[i] = 0.0f;
}

// ---------------------------------------------------------------------------
// Kernel 1: qkv = W_qkv (3072x1024) @ x[b] (1024x2048)
// grid (SEQ/128=16, 3072/128=24, BATCH), block 256
// ---------------------------------------------------------------------------
__global__ __launch_bounds__(256, 2) void qkv_gemm(const float* __restrict__ W,
                                                   const float* __restrict__ X) {
    __shared__ float As[16][132];   // [k][m], padded
    __shared__ float Bs[16][128];   // [k][n]
    const int b  = blockIdx.z;
    const int m0 = blockIdx.y * 128;
    const int n0 = blockIdx.x * 128;
    const float* Xb = X + (size_t)b * CIN * SEQ;
    float*       Yb = g_qkv + (size_t)b * C3 * SEQ;
    const int tid = threadIdx.x;
    const int tx = tid & 15, ty = tid >> 4;

    float acc[8][8];
#pragma unroll
    for (int i = 0; i < 8; i++)
#pragma unroll
        for (int j = 0; j < 8; j++) acc[i][j] = 0.0f;

    for (int k0 = 0; k0 < CIN; k0 += 16) {
        // W tile (128 rows x 16 cols) -> As[k][m] (transposed)
#pragma unroll
        for (int t = 0; t < 2; t++) {
            int i = tid + t * 256;              // 0..511
            int row = i >> 2, kq = (i & 3) << 2;
            float4 w = *reinterpret_cast<const float4*>(W + (size_t)(m0 + row) * CIN + k0 + kq);
            As[kq + 0][row] = w.x; As[kq + 1][row] = w.y;
            As[kq + 2][row] = w.z; As[kq + 3][row] = w.w;
        }
        // X tile (16 rows x 128 cols) -> Bs[k][n]
#pragma unroll
        for (int t = 0; t < 2; t++) {
            int i = tid + t * 256;
            int row = i >> 5, c4 = (i & 31) << 2;
            *reinterpret_cast<float4*>(&Bs[row][c4]) =
                *reinterpret_cast<const float4*>(Xb + (size_t)(k0 + row) * SEQ + n0 + c4);
        }
        __syncthreads();
#pragma unroll
        for (int kk = 0; kk < 16; kk++) {
            float a[8], bb[8];
            *reinterpret_cast<float4*>(a)      = *reinterpret_cast<const float4*>(&As[kk][ty * 8]);
            *reinterpret_cast<float4*>(a + 4)  = *reinterpret_cast<const float4*>(&As[kk][ty * 8 + 4]);
            *reinterpret_cast<float4*>(bb)     = *reinterpret_cast<const float4*>(&Bs[kk][tx * 8]);
            *reinterpret_cast<float4*>(bb + 4) = *reinterpret_cast<const float4*>(&Bs[kk][tx * 8 + 4]);
#pragma unroll
            for (int i = 0; i < 8; i++)
#pragma unroll
                for (int j = 0; j < 8; j++)
                    acc[i][j] = fmaf(a[i], bb[j], acc[i][j]);
        }
        __syncthreads();
    }
#pragma unroll
    for (int i = 0; i < 8; i++) {
        float* yr = Yb + (size_t)(m0 + ty * 8 + i) * SEQ + n0 + tx * 8;
        *reinterpret_cast<float4*>(yr)     = make_float4(acc[i][0], acc[i][1], acc[i][2], acc[i][3]);
        *reinterpret_cast<float4*>(yr + 4) = make_float4(acc[i][4], acc[i][5], acc[i][6], acc[i][7]);
    }
}

// ---------------------------------------------------------------------------
// Kernel 2: M[b,h] += scale * V[b,h] @ K[b,h]^T   (split-K over SEQ, atomics)
// grid (SEQ/256=8, BATCH*NH=32), block 256
// ---------------------------------------------------------------------------
__global__ __launch_bounds__(256, 2) void vk_gemm() {
    __shared__ float As[16][132];   // [s][d] from V
    __shared__ float Bs[16][132];   // [s][e] from K
    const int bh = blockIdx.y;
    const int b = bh >> 3, h = bh & 7;
    const float* Vp = g_qkv + ((size_t)b * C3 + 2048 + h * DH) * SEQ;
    const float* Kp = g_qkv + ((size_t)b * C3 + 1024 + h * DH) * SEQ;
    const int s0 = blockIdx.x * 256;
    const int tid = threadIdx.x;
    const int tx = tid & 15, ty = tid >> 4;

    float acc[8][8];
#pragma unroll
    for (int i = 0; i < 8; i++)
#pragma unroll
        for (int j = 0; j < 8; j++) acc[i][j] = 0.0f;

    for (int k0 = s0; k0 < s0 + 256; k0 += 16) {
#pragma unroll
        for (int t = 0; t < 2; t++) {
            int i = tid + t * 256;
            int row = i >> 2, kq = (i & 3) << 2;      // row = d (or e), kq = s offset
            float4 v = *reinterpret_cast<const float4*>(Vp + (size_t)row * SEQ + k0 + kq);
            As[kq + 0][row] = v.x; As[kq + 1][row] = v.y;
            As[kq + 2][row] = v.z; As[kq + 3][row] = v.w;
            float4 k4 = *reinterpret_cast<const float4*>(Kp + (size_t)row * SEQ + k0 + kq);
            Bs[kq + 0][row] = k4.x; Bs[kq + 1][row] = k4.y;
            Bs[kq + 2][row] = k4.z; Bs[kq + 3][row] = k4.w;
        }
        __syncthreads();
#pragma unroll
        for (int kk = 0; kk < 16; kk++) {
            float a[8], bb[8];
            *reinterpret_cast<float4*>(a)      = *reinterpret_cast<const float4*>(&As[kk][ty * 8]);
            *reinterpret_cast<float4*>(a + 4)  = *reinterpret_cast<const float4*>(&As[kk][ty * 8 + 4]);
            *reinterpret_cast<float4*>(bb)     = *reinterpret_cast<const float4*>(&Bs[kk][tx * 8]);
            *reinterpret_cast<float4*>(bb + 4) = *reinterpret_cast<const float4*>(&Bs[kk][tx * 8 + 4]);
#pragma unroll
            for (int i = 0; i < 8; i++)
#pragma unroll
                for (int j = 0; j < 8; j++)
                    acc[i][j] = fmaf(a[i], bb[j], acc[i][j]);
        }
        __syncthreads();
    }
    float* Mp = g_M + (size_t)bh * DH * DH;
#pragma unroll
    for (int i = 0; i < 8; i++)
#pragma unroll
        for (int j = 0; j < 8; j++)
            atomicAdd(&Mp[(size_t)(ty * 8 + i) * DH + tx * 8 + j], acc[i][j] * SCALE_F);
}

// ---------------------------------------------------------------------------
// Kernel 3: C[b,h] = M[b,h] (128x128) @ Q[b,h] (128x2048)
// grid (SEQ/128=16, BATCH*NH=32), block 256
// ---------------------------------------------------------------------------
__global__ __launch_bounds__(256, 2) void mq_gemm() {
    __shared__ float As[16][132];   // [e][d]
    __shared__ float Bs[16][128];   // [e][s]
    const int bh = blockIdx.y;
    const int b = bh >> 3, h = bh & 7;
    const float* Wm = g_M + (size_t)bh * DH * DH;                 // (d,e) row-major
    const float* Qb = g_qkv + ((size_t)b * C3 + h * DH) * SEQ;    // Q rows
    float*       Cb = g_C + ((size_t)b * CIN + h * DH) * SEQ;
    const int n0 = blockIdx.x * 128;
    const int tid = threadIdx.x;
    const int tx = tid & 15, ty = tid >> 4;

    float acc[8][8];
#pragma unroll
    for (int i = 0; i < 8; i++)
#pragma unroll
        for (int j = 0; j < 8; j++) acc[i][j] = 0.0f;

    for (int k0 = 0; k0 < DH; k0 += 16) {
#pragma unroll
        for (int t = 0; t < 2; t++) {
            int i = tid + t * 256;
            int row = i >> 2, kq = (i & 3) << 2;
            float4 w = *reinterpret_cast<const float4*>(Wm + (size_t)row * DH + k0 + kq);
            As[kq + 0][row] = w.x; As[kq + 1][row] = w.y;
            As[kq + 2][row] = w.z; As[kq + 3][row] = w.w;
        }
#pragma unroll
        for (int t = 0; t < 2; t++) {
            int i = tid + t * 256;
            int row = i >> 5, c4 = (i & 31) << 2;
            *reinterpret_cast<float4*>(&Bs[row][c4]) =
                *reinterpret_cast<const float4*>(Qb + (size_t)(k0 + row) * SEQ + n0 + c4);
        }
        __syncthreads();
#pragma unroll
        for (int kk = 0; kk < 16; kk++) {
            float a[8], bb[8];
            *reinterpret_cast<float4*>(a)      = *reinterpret_cast<const float4*>(&As[kk][ty * 8]);
            *reinterpret_cast<float4*>(a + 4)  = *reinterpret_cast<const float4*>(&As[kk][ty * 8 + 4]);
            *reinterpret_cast<float4*>(bb)     = *reinterpret_cast<const float4*>(&Bs[kk][tx * 8]);
            *reinterpret_cast<float4*>(bb + 4) = *reinterpret_cast<const float4*>(&Bs[kk][tx * 8 + 4]);
#pragma unroll
            for (int i = 0; i < 8; i++)
#pragma unroll
                for (int j = 0; j < 8; j++)
                    acc[i][j] = fmaf(a[i], bb[j], acc[i][j]);
        }
        __syncthreads();
    }
#pragma unroll
    for (int i = 0; i < 8; i++) {
        float* cr = Cb + (size_t)(ty * 8 + i) * SEQ + n0 + tx * 8;
        *reinterpret_cast<float4*>(cr)     = make_float4(acc[i][0], acc[i][1], acc[i][2], acc[i][3]);
        *reinterpret_cast<float4*>(cr + 4) = make_float4(acc[i][4], acc[i][5], acc[i][6], acc[i][7]);
    }
}

// ---------------------------------------------------------------------------
// Kernel 4: out = W_out (1024x1024) @ C[b] (1024x2048)
// grid (SEQ/128=16, 1024/128=8, BATCH), block 256
// ---------------------------------------------------------------------------
__global__ __launch_bounds__(256, 2) void out_gemm(const float* __restrict__ W,
                                                   float* __restrict__ Out) {
    __shared__ float As[16][132];
    __shared__ float Bs[16][128];
    const int b  = blockIdx.z;
    const int m0 = blockIdx.y * 128;
    const int n0 = blockIdx.x * 128;
    const float* Xb = g_C + (size_t)b * CIN * SEQ;
    float*       Yb = Out + (size_t)b * CIN * SEQ;
    const int tid = threadIdx.x;
    const int tx = tid & 15, ty = tid >> 4;

    float acc[8][8];
#pragma unroll
    for (int i = 0; i < 8; i++)
#pragma unroll
        for (int j = 0; j < 8; j++) acc[i][j] = 0.0f;

    for (int k0 = 0; k0 < CIN; k0 += 16) {
#pragma unroll
        for (int t = 0; t < 2; t++) {
            int i = tid + t * 256;
            int row = i >> 2, kq = (i & 3) << 2;
            float4 w = *reinterpret_cast<const float4*>(W + (size_t)(m0 + row) * CIN + k0 + kq);
            As[kq + 0][row] = w.x; As[kq + 1][row] = w.y;
            As[kq + 2][row] = w.z; As[kq + 3][row] = w.w;
        }
#pragma unroll
        for (int t = 0; t < 2; t++) {
            int i = tid + t * 256;
            int row = i >> 5, c4 = (i & 31) << 2;
            *reinterpret_cast<float4*>(&Bs[row][c4]) =
                *reinterpret_cast<const float4*>(Xb + (size_t)(k0 + row) * SEQ + n0 + c4);
        }
        __syncthreads();
#pragma unroll
        for (int kk = 0; kk < 16; kk++) {
            float a[8], bb[8];
            *reinterpret_cast<float4*>(a)      = *reinterpret_cast<const float4*>(&As[kk][ty * 8]);
            *reinterpret_cast<float4*>(a + 4)  = *reinterpret_cast<const float4*>(&As[kk][ty * 8 + 4]);
            *reinterpret_cast<float4*>(bb)     = *reinterpret_cast<const float4*>(&Bs[kk][tx * 8]);
            *reinterpret_cast<float4*>(bb + 4) = *reinterpret_cast<const float4*>(&Bs[kk][tx * 8 + 4]);
#pragma unroll
            for (int i = 0; i < 8; i++)
#pragma unroll
                for (int j = 0; j < 8; j++)
                    acc[i][j] = fmaf(a[i], bb[j], acc[i][j]);
        }
        __syncthreads();
    }
#pragma unroll
    for (int i = 0; i < 8; i++) {
        float* yr = Yb + (size_t)(m0 + ty * 8 + i) * SEQ + n0 + tx * 8;
        *reinterpret_cast<float4*>(yr)     = make_float4(acc[i][0], acc[i][1], acc[i][2], acc[i][3]);
        *reinterpret_cast<float4*>(yr + 4) = make_float4(acc[i][4], acc[i][5], acc[i][6], acc[i][7]);
    }
}

// ---------------------------------------------------------------------------
extern "C" void kernel_launch(void* const* d_in, const int* in_sizes, int n_in,
                              void* d_out, int out_size) {
    // Identify inputs by element count (sizes are unique)
    const float* x = nullptr;
    const float* W_qkv = nullptr;
    const float* W_out = nullptr;
    for (int i = 0; i < n_in; i++) {
        if (in_sizes[i] == BATCH * CIN * SEQ)      x     = (const float*)d_in[i];
        else if (in_sizes[i] == C3 * CIN)          W_qkv = (const float*)d_in[i];
        else if (in_sizes[i] == CIN * CIN)         W_out = (const float*)d_in[i];
    }
    float* out = (float*)d_out;

    zero_M_kernel<<<512, 1024>>>();
    qkv_gemm<<<dim3(SEQ / 128, C3 / 128, BATCH), 256>>>(W_qkv, x);
    vk_gemm<<<dim3(SEQ / 256, BATCH * NH), 256>>>();
    mq_gemm<<<dim3(SEQ / 128, BATCH * NH), 256>>>();
    out_gemm<<<dim3(SEQ / 128, CIN / 128, BATCH), 256>>>(W_out, out);
}

// round 3
// speedup vs baseline: 1.9830x; 1.9830x over previous
#include <cuda_runtime.h>
#include <cuda_bf16.h>
#include <cstdint>

// Problem constants
#define BATCH 4
#define SEQ   2048
#define CIN   1024
#define C3    3072
#define NH    8
#define DH    128
#define SCALE_F 0.08838834764831845f   // 1/sqrt(128)

// ---------------------------------------------------------------------------
// Scratch (device globals — no runtime allocation)
// ---------------------------------------------------------------------------
__device__ float g_qkv[(size_t)BATCH * C3 * SEQ];     // (B, 3072, S)
__device__ float g_M[(size_t)BATCH * NH * DH * DH];   // (B, H, 128, 128)
__device__ float g_C[(size_t)BATCH * CIN * SEQ];      // (B, 1024, S)
__device__ __nv_bfloat16 g_Wq_hi[(size_t)C3 * CIN];
__device__ __nv_bfloat16 g_Wq_lo[(size_t)C3 * CIN];
__device__ __nv_bfloat16 g_Wo_hi[(size_t)CIN * CIN];
__device__ __nv_bfloat16 g_Wo_lo[(size_t)CIN * CIN];

// ---------------------------------------------------------------------------
// PTX helpers: ldmatrix + mma.sync (bf16), legal in compute_103 PTX
// ---------------------------------------------------------------------------
__device__ __forceinline__ uint32_t smem_to_u32(const void* p) {
    uint32_t a;
    asm("{ .reg .u64 t; cvta.to.shared.u64 t, %1; cvt.u32.u64 %0, t; }" : "=r"(a) : "l"(p));
    return a;
}

#define LDSM_X4(r, addr) \
    asm volatile("ldmatrix.sync.aligned.m8n8.x4.shared.b16 {%0,%1,%2,%3}, [%4];" \
                 : "=r"((r)[0]), "=r"((r)[1]), "=r"((r)[2]), "=r"((r)[3]) : "r"(addr))
#define LDSM_X4_T(r, addr) \
    asm volatile("ldmatrix.sync.aligned.m8n8.x4.trans.shared.b16 {%0,%1,%2,%3}, [%4];" \
                 : "=r"((r)[0]), "=r"((r)[1]), "=r"((r)[2]), "=r"((r)[3]) : "r"(addr))
#define MMA_BF16(c, a, b0, b1) \
    asm volatile("mma.sync.aligned.m16n8k16.row.col.f32.bf16.bf16.f32 " \
                 "{%0,%1,%2,%3},{%4,%5,%6,%7},{%8,%9},{%0,%1,%2,%3};" \
                 : "+f"((c)[0]), "+f"((c)[1]), "+f"((c)[2]), "+f"((c)[3]) \
                 : "r"((a)[0]), "r"((a)[1]), "r"((a)[2]), "r"((a)[3]), "r"(b0), "r"(b1))

// ---------------------------------------------------------------------------
// Weight split: fp32 -> bf16 hi + bf16 lo (residual)
// ---------------------------------------------------------------------------
template <int MODE>  // 0: W_qkv, 1: W_out
__global__ void split_w(const float* __restrict__ W, int n4) {
    int i = blockIdx.x * blockDim.x + threadIdx.x;
    if (i >= n4) return;
    __nv_bfloat16* hi = (MODE == 0) ? g_Wq_hi : g_Wo_hi;
    __nv_bfloat16* lo = (MODE == 0) ? g_Wq_lo : g_Wo_lo;
    float4 v = reinterpret_cast<const float4*>(W)[i];
    __nv_bfloat16 h0 = __float2bfloat16(v.x), h1 = __float2bfloat16(v.y);
    __nv_bfloat16 h2 = __float2bfloat16(v.z), h3 = __float2bfloat16(v.w);
    __nv_bfloat162* hp = reinterpret_cast<__nv_bfloat162*>(hi);
    __nv_bfloat162* lp = reinterpret_cast<__nv_bfloat162*>(lo);
    hp[2 * i]     = __nv_bfloat162(h0, h1);
    hp[2 * i + 1] = __nv_bfloat162(h2, h3);
    lp[2 * i]     = __nv_bfloat162(__float2bfloat16(v.x - __bfloat162float(h0)),
                                   __float2bfloat16(v.y - __bfloat162float(h1)));
    lp[2 * i + 1] = __nv_bfloat162(__float2bfloat16(v.z - __bfloat162float(h2)),
                                   __float2bfloat16(v.w - __bfloat162float(h3)));
}

// ---------------------------------------------------------------------------
// mma.sync 3-pass bf16 GEMM:  Y[m][n] = sum_k A[m][k] * B[k][n]
//   A: pre-split bf16 hi/lo, row-major (M x 1024)
//   B: fp32, row-major (1024 x SEQ), split to bf16 hi/lo on smem fill
//   Y: fp32, row-major (M x SEQ)
// Block tile 128x128, K-chunk 32, double-buffered smem, 8 warps (64x32 each).
// ---------------------------------------------------------------------------
#define SMA_STR  40      // A smem row stride (bf16 elems), 80 B  (conflict-free)
#define SMB_STR  136     // B smem row stride (bf16 elems), 272 B (conflict-free)
#define AHI_OFF  0
#define ALO_OFF  10240   // 128*40*2
#define BHI_OFF  20480
#define BLO_OFF  29184   // +32*136*2
#define STAGE_B  37888
#define MMA_SMEM (2 * STAGE_B)   // 75776

__global__ __launch_bounds__(256) void mma_gemm(
    const __nv_bfloat16* __restrict__ Ahi, const __nv_bfloat16* __restrict__ Alo,
    const float* __restrict__ Bg, float* __restrict__ Yg,
    size_t bStride, size_t yStride)
{
    extern __shared__ char smem[];
    const uint32_t sbase = smem_to_u32(smem);
    const int tid  = threadIdx.x;
    const int wid  = tid >> 5, lane = tid & 31;
    const int wm   = wid & 1, wn = wid >> 1;          // warp grid 2(m) x 4(n)
    const int b    = blockIdx.z;
    const int m0   = blockIdx.y * 128;
    const int n0   = blockIdx.x * 128;
    const float* B = Bg + (size_t)b * bStride;
    float*       Y = Yg + (size_t)b * yStride;

    // ldmatrix per-lane address components
    // A (non-trans x4): row = lane&15, col byte = (lane>>4)*16
    const uint32_t aAddr = sbase + (uint32_t)((wm * 64 + (lane & 15)) * (SMA_STR * 2) + (lane >> 4) * 16);
    // B (trans x4): seg = lane>>3: k = (seg&1)*8 + (lane&7); n-off = (seg>>1)*8
    {
    }
    const int seg = lane >> 3;
    const uint32_t bAddr = sbase + (uint32_t)(((seg & 1) * 8 + (lane & 7)) * (SMB_STR * 2)
                                              + (wn * 32 + (seg >> 1) * 8) * 2);

    float acc[4][4][4];
#pragma unroll
    for (int i = 0; i < 4; i++)
#pragma unroll
        for (int j = 0; j < 4; j++)
#pragma unroll
            for (int q = 0; q < 4; q++) acc[i][j][q] = 0.0f;

    // ---- global load helpers (registers) ----
    uint4  pa[4];   // Ahi x2, Alo x2 (each 8 bf16)
    float4 pb[4];   // B fp32

    auto load_global = [&](int s) {
        const int k0 = s * 32;
#pragma unroll
        for (int t = 0; t < 2; t++) {
            int i = tid + t * 256;                // 0..511
            int row = i >> 2, kg = (i & 3) * 8;
            size_t off = (size_t)(m0 + row) * CIN + k0 + kg;
            pa[t]     = *reinterpret_cast<const uint4*>(Ahi + off);
            pa[2 + t] = *reinterpret_cast<const uint4*>(Alo + off);
        }
#pragma unroll
        for (int t = 0; t < 4; t++) {
            int i = tid + t * 256;                // 0..1023
            int row = i >> 5, ng = (i & 31) * 4;
            pb[t] = *reinterpret_cast<const float4*>(B + (size_t)(k0 + row) * SEQ + n0 + ng);
        }
    };
    auto store_stage = [&](int buf) {
        char* sp = smem + buf * STAGE_B;
#pragma unroll
        for (int t = 0; t < 2; t++) {
            int i = tid + t * 256;
            int row = i >> 2, kg = (i & 3) * 8;
            *reinterpret_cast<uint4*>(sp + AHI_OFF + (row * SMA_STR + kg) * 2) = pa[t];
            *reinterpret_cast<uint4*>(sp + ALO_OFF + (row * SMA_STR + kg) * 2) = pa[2 + t];
        }
#pragma unroll
        for (int t = 0; t < 4; t++) {
            int i = tid + t * 256;
            int row = i >> 5, ng = (i & 31) * 4;
            float4 v = pb[t];
            __nv_bfloat16 h0 = __float2bfloat16(v.x), h1 = __float2bfloat16(v.y);
            __nv_bfloat16 h2 = __float2bfloat16(v.z), h3 = __float2bfloat16(v.w);
            char* ph = sp + BHI_OFF + (row * SMB_STR + ng) * 2;
            char* pl = sp + BLO_OFF + (row * SMB_STR + ng) * 2;
            reinterpret_cast<__nv_bfloat162*>(ph)[0] = __nv_bfloat162(h0, h1);
            reinterpret_cast<__nv_bfloat162*>(ph)[1] = __nv_bfloat162(h2, h3);
            reinterpret_cast<__nv_bfloat162*>(pl)[0] =
                __nv_bfloat162(__float2bfloat16(v.x - __bfloat162float(h0)),
                               __float2bfloat16(v.y - __bfloat162float(h1)));
            reinterpret_cast<__nv_bfloat162*>(pl)[1] =
                __nv_bfloat162(__float2bfloat16(v.z - __bfloat162float(h2)),
                               __float2bfloat16(v.w - __bfloat162float(h3)));
        }
    };

    // ---- prologue ----
    load_global(0);
    store_stage(0);
    __syncthreads();

    const int niter = CIN / 32;   // 32
    for (int s = 0; s < niter; s++) {
        const int buf = s & 1;
        if (s + 1 < niter) load_global(s + 1);

        const uint32_t stage = (uint32_t)(buf * STAGE_B);
#pragma unroll
        for (int kk = 0; kk < 2; kk++) {
            uint32_t ah[4][4], al[4][4], bh[2][4], bl[2][4];
#pragma unroll
            for (int i = 0; i < 4; i++)
                LDSM_X4(ah[i], aAddr + stage + AHI_OFF + (uint32_t)(i * 16 * SMA_STR * 2 + kk * 32));
#pragma unroll
            for (int j = 0; j < 2; j++)
                LDSM_X4_T(bh[j], bAddr + stage + BHI_OFF + (uint32_t)(kk * 16 * SMB_STR * 2 + j * 32));
            // pass 1: hi * hi
#pragma unroll
            for (int i = 0; i < 4; i++)
#pragma unroll
                for (int j = 0; j < 4; j++)
                    MMA_BF16(acc[i][j], ah[i], bh[j >> 1][(j & 1) * 2], bh[j >> 1][(j & 1) * 2 + 1]);
            // pass 2: hi * lo
#pragma unroll
            for (int j = 0; j < 2; j++)
                LDSM_X4_T(bl[j], bAddr + stage + BLO_OFF + (uint32_t)(kk * 16 * SMB_STR * 2 + j * 32));
#pragma unroll
            for (int i = 0; i < 4; i++)
#pragma unroll
                for (int j = 0; j < 4; j++)
                    MMA_BF16(acc[i][j], ah[i], bl[j >> 1][(j & 1) * 2], bl[j >> 1][(j & 1) * 2 + 1]);
            // pass 3: lo * hi
#pragma unroll
            for (int i = 0; i < 4; i++)
                LDSM_X4(al[i], aAddr + stage + ALO_OFF + (uint32_t)(i * 16 * SMA_STR * 2 + kk * 32));
#pragma unroll
            for (int i = 0; i < 4; i++)
#pragma unroll
                for (int j = 0; j < 4; j++)
                    MMA_BF16(acc[i][j], al[i], bh[j >> 1][(j & 1) * 2], bh[j >> 1][(j & 1) * 2 + 1]);
        }

        if (s + 1 < niter) store_stage(buf ^ 1);
        __syncthreads();
    }

    // ---- epilogue ----
    const int g = lane >> 2, t4 = lane & 3;
#pragma unroll
    for (int i = 0; i < 4; i++) {
        int m = m0 + wm * 64 + i * 16 + g;
#pragma unroll
        for (int j = 0; j < 4; j++) {
            int n = n0 + wn * 32 + j * 8 + t4 * 2;
            *reinterpret_cast<float2*>(&Y[(size_t)m * SEQ + n]) =
                make_float2(acc[i][j][0], acc[i][j][1]);
            *reinterpret_cast<float2*>(&Y[(size_t)(m + 8) * SEQ + n]) =
                make_float2(acc[i][j][2], acc[i][j][3]);
        }
    }
}

// ---------------------------------------------------------------------------
// zero M
// ---------------------------------------------------------------------------
__global__ void zero_M_kernel() {
    int i = blockIdx.x * blockDim.x + threadIdx.x;
    if (i < BATCH * NH * DH * DH) g_M[i] = 0.0f;
}

// ---------------------------------------------------------------------------
// M[b,h] += scale * V[b,h] @ K[b,h]^T   (split-K over SEQ, atomics)  [fp32]
// ---------------------------------------------------------------------------
__global__ __launch_bounds__(256, 2) void vk_gemm() {
    __shared__ float As[16][132];
    __shared__ float Bs[16][132];
    const int bh = blockIdx.y;
    const int b = bh >> 3, h = bh & 7;
    const float* Vp = g_qkv + ((size_t)b * C3 + 2048 + h * DH) * SEQ;
    const float* Kp = g_qkv + ((size_t)b * C3 + 1024 + h * DH) * SEQ;
    const int s0 = blockIdx.x * 256;
    const int tid = threadIdx.x;
    const int tx = tid & 15, ty = tid >> 4;

    float acc[8][8];
#pragma unroll
    for (int i = 0; i < 8; i++)
#pragma unroll
        for (int j = 0; j < 8; j++) acc[i][j] = 0.0f;

    for (int k0 = s0; k0 < s0 + 256; k0 += 16) {
#pragma unroll
        for (int t = 0; t < 2; t++) {
            int i = tid + t * 256;
            int row = i >> 2, kq = (i & 3) << 2;
            float4 v = *reinterpret_cast<const float4*>(Vp + (size_t)row * SEQ + k0 + kq);
            As[kq + 0][row] = v.x; As[kq + 1][row] = v.y;
            As[kq + 2][row] = v.z; As[kq + 3][row] = v.w;
            float4 k4 = *reinterpret_cast<const float4*>(Kp + (size_t)row * SEQ + k0 + kq);
            Bs[kq + 0][row] = k4.x; Bs[kq + 1][row] = k4.y;
            Bs[kq + 2][row] = k4.z; Bs[kq + 3][row] = k4.w;
        }
        __syncthreads();
#pragma unroll
        for (int kk = 0; kk < 16; kk++) {
            float a[8], bb[8];
            *reinterpret_cast<float4*>(a)      = *reinterpret_cast<const float4*>(&As[kk][ty * 8]);
            *reinterpret_cast<float4*>(a + 4)  = *reinterpret_cast<const float4*>(&As[kk][ty * 8 + 4]);
            *reinterpret_cast<float4*>(bb)     = *reinterpret_cast<const float4*>(&Bs[kk][tx * 8]);
            *reinterpret_cast<float4*>(bb + 4) = *reinterpret_cast<const float4*>(&Bs[kk][tx * 8 + 4]);
#pragma unroll
            for (int i = 0; i < 8; i++)
#pragma unroll
                for (int j = 0; j < 8; j++)
                    acc[i][j] = fmaf(a[i], bb[j], acc[i][j]);
        }
        __syncthreads();
    }
    float* Mp = g_M + (size_t)bh * DH * DH;
#pragma unroll
    for (int i = 0; i < 8; i++)
#pragma unroll
        for (int j = 0; j < 8; j++)
            atomicAdd(&Mp[(size_t)(ty * 8 + i) * DH + tx * 8 + j], acc[i][j] * SCALE_F);
}

// ---------------------------------------------------------------------------
// C[b,h] = M[b,h] (128x128) @ Q[b,h] (128x2048)  [fp32]
// ---------------------------------------------------------------------------
__global__ __launch_bounds__(256, 2) void mq_gemm() {
    __shared__ float As[16][132];
    __shared__ float Bs[16][128];
    const int bh = blockIdx.y;
    const int b = bh >> 3, h = bh & 7;
    const float* Wm = g_M + (size_t)bh * DH * DH;
    const float* Qb = g_qkv + ((size_t)b * C3 + h * DH) * SEQ;
    float*       Cb = g_C + ((size_t)b * CIN + h * DH) * SEQ;
    const int n0 = blockIdx.x * 128;
    const int tid = threadIdx.x;
    const int tx = tid & 15, ty = tid >> 4;

    float acc[8][8];
#pragma unroll
    for (int i = 0; i < 8; i++)
#pragma unroll
        for (int j = 0; j < 8; j++) acc[i][j] = 0.0f;

    for (int k0 = 0; k0 < DH; k0 += 16) {
#pragma unroll
        for (int t = 0; t < 2; t++) {
            int i = tid + t * 256;
            int row = i >> 2, kq = (i & 3) << 2;
            float4 w = *reinterpret_cast<const float4*>(Wm + (size_t)row * DH + k0 + kq);
            As[kq + 0][row] = w.x; As[kq + 1][row] = w.y;
            As[kq + 2][row] = w.z; As[kq + 3][row] = w.w;
        }
#pragma unroll
        for (int t = 0; t < 2; t++) {
            int i = tid + t * 256;
            int row = i >> 5, c4 = (i & 31) << 2;
            *reinterpret_cast<float4*>(&Bs[row][c4]) =
                *reinterpret_cast<const float4*>(Qb + (size_t)(k0 + row) * SEQ + n0 + c4);
        }
        __syncthreads();
#pragma unroll
        for (int kk = 0; kk < 16; kk++) {
            float a[8], bb[8];
            *reinterpret_cast<float4*>(a)      = *reinterpret_cast<const float4*>(&As[kk][ty * 8]);
            *reinterpret_cast<float4*>(a + 4)  = *reinterpret_cast<const float4*>(&As[kk][ty * 8 + 4]);
            *reinterpret_cast<float4*>(bb)     = *reinterpret_cast<const float4*>(&Bs[kk][tx * 8]);
            *reinterpret_cast<float4*>(bb + 4) = *reinterpret_cast<const float4*>(&Bs[kk][tx * 8 + 4]);
#pragma unroll
            for (int i = 0; i < 8; i++)
#pragma unroll
                for (int j = 0; j < 8; j++)
                    acc[i][j] = fmaf(a[i], bb[j], acc[i][j]);
        }
        __syncthreads();
    }
#pragma unroll
    for (int i = 0; i < 8; i++) {
        float* cr = Cb + (size_t)(ty * 8 + i) * SEQ + n0 + tx * 8;
        *reinterpret_cast<float4*>(cr)     = make_float4(acc[i][0], acc[i][1], acc[i][2], acc[i][3]);
        *reinterpret_cast<float4*>(cr + 4) = make_float4(acc[i][4], acc[i][5], acc[i][6], acc[i][7]);
    }
}

// ---------------------------------------------------------------------------
extern "C" void kernel_launch(void* const* d_in, const int* in_sizes, int n_in,
                              void* d_out, int out_size) {
    const float* x = nullptr;
    const float* W_qkv = nullptr;
    const float* W_out = nullptr;
    for (int i = 0; i < n_in; i++) {
        if (in_sizes[i] == BATCH * CIN * SEQ)      x     = (const float*)d_in[i];
        else if (in_sizes[i] == C3 * CIN)          W_qkv = (const float*)d_in[i];
        else if (in_sizes[i] == CIN * CIN)         W_out = (const float*)d_in[i];
    }
    float* out = (float*)d_out;

    static bool attr_set = false;
    if (!attr_set) {
        cudaFuncSetAttribute(mma_gemm, cudaFuncAttributeMaxDynamicSharedMemorySize, MMA_SMEM);
        attr_set = true;
    }

    // Weight splits (cheap; deterministic every call)
    split_w<0><<<(C3 * CIN / 4 + 255) / 256, 256>>>(W_qkv, C3 * CIN / 4);
    split_w<1><<<(CIN * CIN / 4 + 255) / 256, 256>>>(W_out, CIN * CIN / 4);

    // QKV projection: g_qkv = W_qkv @ x   (tensor cores, 3-pass bf16)
    // A hi/lo = g_Wq (3072x1024), B = x (1024 x 2048 per batch)
    {
        __nv_bfloat16 *ahi = nullptr, *alo = nullptr;
        cudaGetSymbolAddress((void**)&ahi, g_Wq_hi);
        cudaGetSymbolAddress((void**)&alo, g_Wq_lo);
        float* y = nullptr;
        cudaGetSymbolAddress((void**)&y, g_qkv);
        mma_gemm<<<dim3(SEQ / 128, C3 / 128, BATCH), 256, MMA_SMEM>>>(
            ahi, alo, x, y, (size_t)CIN * SEQ, (size_t)C3 * SEQ);
    }

    // Linear attention core (fp32 SIMT)
    zero_M_kernel<<<512, 1024>>>();
    vk_gemm<<<dim3(SEQ / 256, BATCH * NH), 256>>>();
    mq_gemm<<<dim3(SEQ / 128, BATCH * NH), 256>>>();

    // Output projection: out = W_out @ C
    {
        __nv_bfloat16 *ahi = nullptr, *alo = nullptr;
        cudaGetSymbolAddress((void**)&ahi, g_Wo_hi);
        cudaGetSymbolAddress((void**)&alo, g_Wo_lo);
        float* bsrc = nullptr;
        cudaGetSymbolAddress((void**)&bsrc, g_C);
        mma_gemm<<<dim3(SEQ / 128, CIN / 128, BATCH), 256, MMA_SMEM>>>(
            ahi, alo, bsrc, out, (size_t)CIN * SEQ, (size_t)CIN * SEQ);
    }
}

// round 4
// speedup vs baseline: 2.4708x; 1.2460x over previous
#include <cuda_runtime.h>
#include <cuda_bf16.h>
#include <cstdint>

// Problem constants
#define BATCH 4
#define SEQ   2048
#define CIN   1024
#define C3    3072
#define NH    8
#define DH    128
#define SCALE_F 0.08838834764831845f   // 1/sqrt(128)

typedef __nv_bfloat16 bf16;

// ---------------------------------------------------------------------------
// Scratch (device globals — no runtime allocation)
// ---------------------------------------------------------------------------
__device__ bf16 g_Wq_hi[(size_t)C3 * CIN];
__device__ bf16 g_Wq_lo[(size_t)C3 * CIN];
__device__ bf16 g_Wo_hi[(size_t)CIN * CIN];
__device__ bf16 g_Wo_lo[(size_t)CIN * CIN];
__device__ bf16 g_x_hi[(size_t)BATCH * CIN * SEQ];
__device__ bf16 g_x_lo[(size_t)BATCH * CIN * SEQ];
__device__ bf16 g_qkv_hi[(size_t)BATCH * C3 * SEQ];
__device__ bf16 g_qkv_lo[(size_t)BATCH * C3 * SEQ];
__device__ float g_M[(size_t)BATCH * NH * DH * DH];
__device__ bf16 g_M_hi[(size_t)BATCH * NH * DH * DH];
__device__ bf16 g_M_lo[(size_t)BATCH * NH * DH * DH];
__device__ bf16 g_C_hi[(size_t)BATCH * CIN * SEQ];
__device__ bf16 g_C_lo[(size_t)BATCH * CIN * SEQ];

// ---------------------------------------------------------------------------
// PTX helpers (sm_80-era features: legal in compute_103 PTX)
// ---------------------------------------------------------------------------
__device__ __forceinline__ uint32_t smem_to_u32(const void* p) {
    uint32_t a;
    asm("{ .reg .u64 t; cvta.to.shared.u64 t, %1; cvt.u32.u64 %0, t; }" : "=r"(a) : "l"(p));
    return a;
}
#define LDSM_X4(r, addr) \
    asm volatile("ldmatrix.sync.aligned.m8n8.x4.shared.b16 {%0,%1,%2,%3}, [%4];" \
                 : "=r"((r)[0]), "=r"((r)[1]), "=r"((r)[2]), "=r"((r)[3]) : "r"(addr))
#define LDSM_X4_T(r, addr) \
    asm volatile("ldmatrix.sync.aligned.m8n8.x4.trans.shared.b16 {%0,%1,%2,%3}, [%4];" \
                 : "=r"((r)[0]), "=r"((r)[1]), "=r"((r)[2]), "=r"((r)[3]) : "r"(addr))
#define MMA_BF16(c, a, b0, b1) \
    asm volatile("mma.sync.aligned.m16n8k16.row.col.f32.bf16.bf16.f32 " \
                 "{%0,%1,%2,%3},{%4,%5,%6,%7},{%8,%9},{%0,%1,%2,%3};" \
                 : "+f"((c)[0]), "+f"((c)[1]), "+f"((c)[2]), "+f"((c)[3]) \
                 : "r"((a)[0]), "r"((a)[1]), "r"((a)[2]), "r"((a)[3]), "r"(b0), "r"(b1))
#define CP_ASYNC16(dst, src) \
    asm volatile("cp.async.cg.shared.global [%0], [%1], 16;" :: "r"(dst), "l"(src) : "memory")
#define CP_COMMIT() asm volatile("cp.async.commit_group;" ::: "memory")
#define CP_WAIT1()  asm volatile("cp.async.wait_group 1;" ::: "memory")

// ---------------------------------------------------------------------------
// fp32 -> bf16 hi + lo(residual) split, float4 vectorized
// ---------------------------------------------------------------------------
__global__ void split_pair(const float* __restrict__ src, bf16* __restrict__ hi,
                           bf16* __restrict__ lo, int n4) {
    int i = blockIdx.x * blockDim.x + threadIdx.x;
    if (i >= n4) return;
    float4 v = reinterpret_cast<const float4*>(src)[i];
    bf16 h0 = __float2bfloat16(v.x), h1 = __float2bfloat16(v.y);
    bf16 h2 = __float2bfloat16(v.z), h3 = __float2bfloat16(v.w);
    __nv_bfloat162* hp = reinterpret_cast<__nv_bfloat162*>(hi);
    __nv_bfloat162* lp = reinterpret_cast<__nv_bfloat162*>(lo);
    hp[2 * i]     = __nv_bfloat162(h0, h1);
    hp[2 * i + 1] = __nv_bfloat162(h2, h3);
    lp[2 * i]     = __nv_bfloat162(__float2bfloat16(v.x - __bfloat162float(h0)),
                                   __float2bfloat16(v.y - __bfloat162float(h1)));
    lp[2 * i + 1] = __nv_bfloat162(__float2bfloat16(v.z - __bfloat162float(h2)),
                                   __float2bfloat16(v.w - __bfloat162float(h3)));
}

__global__ void zero_M_kernel() {
    int i = blockIdx.x * blockDim.x + threadIdx.x;
    if (i < BATCH * NH * DH * DH) g_M[i] = 0.0f;
}

// ---------------------------------------------------------------------------
// Generic 3-pass bf16 HMMA GEMM, 128x128 tile, K-chunk 32, cp.async 3-stage.
// MODE 0: qkv = Wq @ x            (B k-major/trans, EPI split)   grid(16,24,4)
// MODE 1: M  += scale * V @ K^T   (B n-major,       EPI atomic)  grid(1, 4,32)
// MODE 2: C  = M @ Q              (B k-major/trans, EPI split)   grid(16,1,32)
// MODE 3: out = Wo @ C            (B k-major/trans, EPI fp32)    grid(16, 8,4)
// ---------------------------------------------------------------------------
template <int MODE>
__global__ __launch_bounds__(256) void hgemm(float* __restrict__ OutExt) {
    constexpr bool BM0   = (MODE != 1);                     // B trans (k-major) path
    constexpr int  KLEN  = (MODE == 1) ? 512 : (MODE == 2 ? 128 : 1024);
    constexpr int  LDA   = (MODE == 1) ? SEQ : (MODE == 2 ? DH : CIN);
    constexpr int  LDB   = SEQ;
    constexpr int  LDY   = (MODE == 1) ? DH : SEQ;
    constexpr uint32_t AHI = 0, ALO = 10240, BHI = 20480;
    constexpr uint32_t BT  = BM0 ? 8704u : 10240u;          // B tile bytes
    constexpr uint32_t BLO = BHI + BT;
    constexpr uint32_t STAGE = BLO + BT;
    constexpr int NIT = KLEN / 32;

    extern __shared__ char smem[];
    const uint32_t sbase = smem_to_u32(smem);
    const int tid = threadIdx.x;
    const int lane = tid & 31, wid = tid >> 5;
    const int wm = wid & 1, wn = wid >> 1;
    const int z  = blockIdx.z;
    const int m0 = (MODE == 0 || MODE == 3) ? blockIdx.y * 128 : 0;
    const int n0 = blockIdx.x * 128;
    const int kStart = (MODE == 1) ? blockIdx.y * 512 : 0;

    const bf16 *Ahi_, *Alo_, *Bhi_, *Blo_;
    bf16 *Yhi_ = nullptr, *Ylo_ = nullptr;
    float* Yf_ = nullptr;
    if (MODE == 0) {
        Ahi_ = g_Wq_hi; Alo_ = g_Wq_lo;
        Bhi_ = g_x_hi + (size_t)z * CIN * SEQ; Blo_ = g_x_lo + (size_t)z * CIN * SEQ;
        Yhi_ = g_qkv_hi + (size_t)z * C3 * SEQ; Ylo_ = g_qkv_lo + (size_t)z * C3 * SEQ;
    } else if (MODE == 1) {
        int b = z >> 3, h = z & 7;
        size_t vo = ((size_t)b * C3 + 2 * CIN + h * DH) * SEQ;
        size_t ko = ((size_t)b * C3 + CIN + h * DH) * SEQ;
        Ahi_ = g_qkv_hi + vo; Alo_ = g_qkv_lo + vo;
        Bhi_ = g_qkv_hi + ko; Blo_ = g_qkv_lo + ko;
        Yf_  = g_M + (size_t)z * DH * DH;
    } else if (MODE == 2) {
        int b = z >> 3, h = z & 7;
        Ahi_ = g_M_hi + (size_t)z * DH * DH; Alo_ = g_M_lo + (size_t)z * DH * DH;
        size_t qo = ((size_t)b * C3 + h * DH) * SEQ;
        Bhi_ = g_qkv_hi + qo; Blo_ = g_qkv_lo + qo;
        size_t co = ((size_t)b * CIN + h * DH) * SEQ;
        Yhi_ = g_C_hi + co; Ylo_ = g_C_lo + co;
    } else {
        Ahi_ = g_Wo_hi; Alo_ = g_Wo_lo;
        Bhi_ = g_C_hi + (size_t)z * CIN * SEQ; Blo_ = g_C_lo + (size_t)z * CIN * SEQ;
        Yf_  = OutExt + (size_t)z * CIN * SEQ;
    }

    // ldmatrix base addresses (tile-relative)
    const uint32_t aAddr = (uint32_t)((wm * 64 + (lane & 15)) * 80 + (lane >> 4) * 16);
    uint32_t bAddr;
    if (BM0) {
        int seg = lane >> 3;
        bAddr = (uint32_t)(((seg & 1) * 8 + (lane & 7)) * 272 + (wn * 32 + (seg >> 1) * 8) * 2);
    } else {
        bAddr = (uint32_t)((wn * 32 + ((lane >> 4) << 3) + (lane & 7)) * 80 + ((lane >> 3) & 1) * 16);
    }

    float acc[4][4][4];
#pragma unroll
    for (int i = 0; i < 4; i++)
#pragma unroll
        for (int j = 0; j < 4; j++)
#pragma unroll
            for (int q = 0; q < 4; q++) acc[i][j][q] = 0.0f;

    auto fill = [&](int s) {
        const uint32_t sp = sbase + (uint32_t)((s % 3) * STAGE);
        const int k0 = kStart + s * 32;
#pragma unroll
        for (int t = 0; t < 2; t++) {
            int c = tid + t * 256;                 // 0..511
            int row = c >> 2, ke = (c & 3) * 8;
            size_t go = (size_t)(m0 + row) * LDA + k0 + ke;
            CP_ASYNC16(sp + AHI + (uint32_t)(row * 80 + ke * 2), Ahi_ + go);
            CP_ASYNC16(sp + ALO + (uint32_t)(row * 80 + ke * 2), Alo_ + go);
        }
        if (BM0) {
#pragma unroll
            for (int t = 0; t < 2; t++) {
                int c = tid + t * 256;
                int row = c >> 4, ne = (c & 15) * 8;
                size_t go = (size_t)(k0 + row) * LDB + n0 + ne;
                CP_ASYNC16(sp + BHI + (uint32_t)(row * 272 + ne * 2), Bhi_ + go);
                CP_ASYNC16(sp + BLO + (uint32_t)(row * 272 + ne * 2), Blo_ + go);
            }
        } else {
#pragma unroll
            for (int t = 0; t < 2; t++) {
                int c = tid + t * 256;
                int row = c >> 2, ke = (c & 3) * 8;
                size_t go = (size_t)(n0 + row) * LDB + k0 + ke;
                CP_ASYNC16(sp + BHI + (uint32_t)(row * 80 + ke * 2), Bhi_ + go);
                CP_ASYNC16(sp + BLO + (uint32_t)(row * 80 + ke * 2), Blo_ + go);
            }
        }
    };

    // prologue: 2 stages in flight
    fill(0); CP_COMMIT();
    fill(1); CP_COMMIT();

    for (int s = 0; s < NIT; s++) {
        CP_WAIT1();
        __syncthreads();
        if (s + 2 < NIT) fill(s + 2);
        CP_COMMIT();

        const uint32_t st = sbase + (uint32_t)((s % 3) * STAGE);
#pragma unroll
        for (int kk = 0; kk < 2; kk++) {
            uint32_t ah[4][4], al[4][4], bh[2][4], bl[2][4];
#pragma unroll
            for (int i = 0; i < 4; i++)
                LDSM_X4(ah[i], st + AHI + aAddr + (uint32_t)(i * (16 * 80) + kk * 32));
#pragma unroll
            for (int j2 = 0; j2 < 2; j2++) {
                if (BM0) LDSM_X4_T(bh[j2], st + BHI + bAddr + (uint32_t)(kk * (16 * 272) + j2 * 32));
                else     LDSM_X4  (bh[j2], st + BHI + bAddr + (uint32_t)(j2 * (16 * 80) + kk * 32));
            }
            // pass 1: hi*hi
#pragma unroll
            for (int i = 0; i < 4; i++)
#pragma unroll
                for (int j = 0; j < 4; j++)
                    MMA_BF16(acc[i][j], ah[i], bh[j >> 1][(j & 1) * 2], bh[j >> 1][(j & 1) * 2 + 1]);
            // pass 2: hi*lo
#pragma unroll
            for (int j2 = 0; j2 < 2; j2++) {
                if (BM0) LDSM_X4_T(bl[j2], st + BLO + bAddr + (uint32_t)(kk * (16 * 272) + j2 * 32));
                else     LDSM_X4  (bl[j2], st + BLO + bAddr + (uint32_t)(j2 * (16 * 80) + kk * 32));
            }
#pragma unroll
            for (int i = 0; i < 4; i++)
#pragma unroll
                for (int j = 0; j < 4; j++)
                    MMA_BF16(acc[i][j], ah[i], bl[j >> 1][(j & 1) * 2], bl[j >> 1][(j & 1) * 2 + 1]);
            // pass 3: lo*hi
#pragma unroll
            for (int i = 0; i < 4; i++)
                LDSM_X4(al[i], st + ALO + aAddr + (uint32_t)(i * (16 * 80) + kk * 32));
#pragma unroll
            for (int i = 0; i < 4; i++)
#pragma unroll
                for (int j = 0; j < 4; j++)
                    MMA_BF16(acc[i][j], al[i], bh[j >> 1][(j & 1) * 2], bh[j >> 1][(j & 1) * 2 + 1]);
        }
        __syncthreads();
    }

    // ---- epilogue ----
    const int g = lane >> 2, t4 = lane & 3;
#pragma unroll
    for (int i = 0; i < 4; i++) {
        int m = m0 + wm * 64 + i * 16 + g;
#pragma unroll
        for (int j = 0; j < 4; j++) {
            int n = n0 + wn * 32 + j * 8 + t4 * 2;
            if (MODE == 1) {
                int ml = m - m0;
                atomicAdd(&Yf_[(size_t)ml * LDY + n],       acc[i][j][0] * SCALE_F);
                atomicAdd(&Yf_[(size_t)ml * LDY + n + 1],   acc[i][j][1] * SCALE_F);
                atomicAdd(&Yf_[(size_t)(ml + 8) * LDY + n],     acc[i][j][2] * SCALE_F);
                atomicAdd(&Yf_[(size_t)(ml + 8) * LDY + n + 1], acc[i][j][3] * SCALE_F);
            } else if (MODE == 3) {
                *reinterpret_cast<float2*>(&Yf_[(size_t)m * LDY + n]) =
                    make_float2(acc[i][j][0], acc[i][j][1]);
                *reinterpret_cast<float2*>(&Yf_[(size_t)(m + 8) * LDY + n]) =
                    make_float2(acc[i][j][2], acc[i][j][3]);
            } else {
                // split store (hi/lo bf16)
#pragma unroll
                for (int half = 0; half < 2; half++) {
                    float v0 = acc[i][j][half * 2], v1 = acc[i][j][half * 2 + 1];
                    bf16 h0 = __float2bfloat16(v0), h1 = __float2bfloat16(v1);
                    size_t off = (size_t)(m + half * 8) * LDY + n;
                    *reinterpret_cast<__nv_bfloat162*>(&Yhi_[off]) = __nv_bfloat162(h0, h1);
                    *reinterpret_cast<__nv_bfloat162*>(&Ylo_[off]) =
                        __nv_bfloat162(__float2bfloat16(v0 - __bfloat162float(h0)),
                                       __float2bfloat16(v1 - __bfloat162float(h1)));
                }
            }
        }
    }
}

#define SMEM_BM0 (3 * 37888)   // 113664
#define SMEM_BM1 (3 * 40960)   // 122880

// ---------------------------------------------------------------------------
extern "C" void kernel_launch(void* const* d_in, const int* in_sizes, int n_in,
                              void* d_out, int out_size) {
    const float* x = nullptr;
    const float* W_qkv = nullptr;
    const float* W_out = nullptr;
    for (int i = 0; i < n_in; i++) {
        if (in_sizes[i] == BATCH * CIN * SEQ)      x     = (const float*)d_in[i];
        else if (in_sizes[i] == C3 * CIN)          W_qkv = (const float*)d_in[i];
        else if (in_sizes[i] == CIN * CIN)         W_out = (const float*)d_in[i];
    }
    float* out = (float*)d_out;

    cudaFuncSetAttribute(hgemm<0>, cudaFuncAttributeMaxDynamicSharedMemorySize, SMEM_BM0);
    cudaFuncSetAttribute(hgemm<1>, cudaFuncAttributeMaxDynamicSharedMemorySize, SMEM_BM1);
    cudaFuncSetAttribute(hgemm<2>, cudaFuncAttributeMaxDynamicSharedMemorySize, SMEM_BM0);
    cudaFuncSetAttribute(hgemm<3>, cudaFuncAttributeMaxDynamicSharedMemorySize, SMEM_BM0);

    // Symbol addresses for split kernels
    bf16 *pWqH, *pWqL, *pWoH, *pWoL, *pXH, *pXL, *pMH, *pML;
    float* pM;
    cudaGetSymbolAddress((void**)&pWqH, g_Wq_hi);
    cudaGetSymbolAddress((void**)&pWqL, g_Wq_lo);
    cudaGetSymbolAddress((void**)&pWoH, g_Wo_hi);
    cudaGetSymbolAddress((void**)&pWoL, g_Wo_lo);
    cudaGetSymbolAddress((void**)&pXH,  g_x_hi);
    cudaGetSymbolAddress((void**)&pXL,  g_x_lo);
    cudaGetSymbolAddress((void**)&pM,   g_M);
    cudaGetSymbolAddress((void**)&pMH,  g_M_hi);
    cudaGetSymbolAddress((void**)&pML,  g_M_lo);

    // Input splits
    split_pair<<<(C3 * CIN / 4 + 255) / 256, 256>>>(W_qkv, pWqH, pWqL, C3 * CIN / 4);
    split_pair<<<(CIN * CIN / 4 + 255) / 256, 256>>>(W_out, pWoH, pWoL, CIN * CIN / 4);
    split_pair<<<(BATCH * CIN * SEQ / 4 + 255) / 256, 256>>>(x, pXH, pXL, BATCH * CIN * SEQ / 4);

    // QKV projection
    hgemm<0><<<dim3(SEQ / 128, C3 / 128, BATCH), 256, SMEM_BM0>>>(nullptr);

    // Linear attention core: M = scale * V K^T, then C = M Q
    zero_M_kernel<<<512, 1024>>>();
    hgemm<1><<<dim3(1, 4, BATCH * NH), 256, SMEM_BM1>>>(nullptr);
    split_pair<<<(BATCH * NH * DH * DH / 4 + 255) / 256, 256>>>(pM, pMH, pML, BATCH * NH * DH * DH / 4);
    hgemm<2><<<dim3(SEQ / 128, 1, BATCH * NH), 256, SMEM_BM0>>>(nullptr);

    // Output projection
    hgemm<3><<<dim3(SEQ / 128, CIN / 128, BATCH), 256, SMEM_BM0>>>(out);
}

// round 8
// speedup vs baseline: 2.5076x; 1.0149x over previous
#include <cuda_runtime.h>
#include <cuda_bf16.h>
#include <cstdint>

// Problem constants
#define BATCH 4
#define SEQ   2048
#define CIN   1024
#define C3    3072
#define NH    8
#define DH    128
#define SCALE_F 0.08838834764831845f   // 1/sqrt(128)

typedef __nv_bfloat16 bf16;

// ---------------------------------------------------------------------------
// Scratch (device globals — no runtime allocation)
// ---------------------------------------------------------------------------
__device__ bf16 g_Wq_hi[(size_t)C3 * CIN];
__device__ bf16 g_Wq_lo[(size_t)C3 * CIN];
__device__ bf16 g_Wo_hi[(size_t)CIN * CIN];
__device__ bf16 g_Wo_lo[(size_t)CIN * CIN];
__device__ bf16 g_x_hi[(size_t)BATCH * CIN * SEQ];
__device__ bf16 g_x_lo[(size_t)BATCH * CIN * SEQ];
__device__ bf16 g_qkv_hi[(size_t)BATCH * C3 * SEQ];
__device__ bf16 g_qkv_lo[(size_t)BATCH * C3 * SEQ];
__device__ float g_M[(size_t)BATCH * NH * DH * DH];
__device__ bf16 g_M_hi[(size_t)BATCH * NH * DH * DH];
__device__ bf16 g_M_lo[(size_t)BATCH * NH * DH * DH];
__device__ bf16 g_C_hi[(size_t)BATCH * CIN * SEQ];
__device__ bf16 g_C_lo[(size_t)BATCH * CIN * SEQ];

// ---------------------------------------------------------------------------
// PTX helpers (sm_80-era features: legal in compute_103 PTX)
// ---------------------------------------------------------------------------
__device__ __forceinline__ uint32_t smem_to_u32(const void* p) {
    uint32_t a;
    asm("{ .reg .u64 t; cvta.to.shared.u64 t, %1; cvt.u32.u64 %0, t; }" : "=r"(a) : "l"(p));
    return a;
}
#define LDSM_X4(r, addr) \
    asm volatile("ldmatrix.sync.aligned.m8n8.x4.shared.b16 {%0,%1,%2,%3}, [%4];" \
                 : "=r"((r)[0]), "=r"((r)[1]), "=r"((r)[2]), "=r"((r)[3]) : "r"(addr))
#define LDSM_X4_T(r, addr) \
    asm volatile("ldmatrix.sync.aligned.m8n8.x4.trans.shared.b16 {%0,%1,%2,%3}, [%4];" \
                 : "=r"((r)[0]), "=r"((r)[1]), "=r"((r)[2]), "=r"((r)[3]) : "r"(addr))
#define MMA_BF16(c, a, b0, b1) \
    asm volatile("mma.sync.aligned.m16n8k16.row.col.f32.bf16.bf16.f32 " \
                 "{%0,%1,%2,%3},{%4,%5,%6,%7},{%8,%9},{%0,%1,%2,%3};" \
                 : "+f"((c)[0]), "+f"((c)[1]), "+f"((c)[2]), "+f"((c)[3]) \
                 : "r"((a)[0]), "r"((a)[1]), "r"((a)[2]), "r"((a)[3]), "r"(b0), "r"(b1))
#define CP_ASYNC16(dst, src) \
    asm volatile("cp.async.cg.shared.global [%0], [%1], 16;" :: "r"(dst), "l"(src) : "memory")
#define CP_COMMIT() asm volatile("cp.async.commit_group;" ::: "memory")
#define CP_WAIT1()  asm volatile("cp.async.wait_group 1;" ::: "memory")
#define CP_WAIT0()  asm volatile("cp.async.wait_group 0;" ::: "memory")

// ---------------------------------------------------------------------------
// fp32 -> bf16 hi + lo(residual) split, float4 vectorized
// ---------------------------------------------------------------------------
__global__ void split_pair(const float* __restrict__ src, bf16* __restrict__ hi,
                           bf16* __restrict__ lo, int n4) {
    int i = blockIdx.x * blockDim.x + threadIdx.x;
    if (i >= n4) return;
    float4 v = reinterpret_cast<const float4*>(src)[i];
    bf16 h0 = __float2bfloat16(v.x), h1 = __float2bfloat16(v.y);
    bf16 h2 = __float2bfloat16(v.z), h3 = __float2bfloat16(v.w);
    __nv_bfloat162* hp = reinterpret_cast<__nv_bfloat162*>(hi);
    __nv_bfloat162* lp = reinterpret_cast<__nv_bfloat162*>(lo);
    hp[2 * i]     = __nv_bfloat162(h0, h1);
    hp[2 * i + 1] = __nv_bfloat162(h2, h3);
    lp[2 * i]     = __nv_bfloat162(__float2bfloat16(v.x - __bfloat162float(h0)),
                                   __float2bfloat16(v.y - __bfloat162float(h1)));
    lp[2 * i + 1] = __nv_bfloat162(__float2bfloat16(v.z - __bfloat162float(h2)),
                                   __float2bfloat16(v.w - __bfloat162float(h3)));
}

__global__ void zero_M_kernel() {
    int i = blockIdx.x * blockDim.x + threadIdx.x;
    if (i < BATCH * NH * DH * DH) g_M[i] = 0.0f;
}

// ---------------------------------------------------------------------------
// Generic 3-pass bf16 HMMA GEMM, 128x128 tile, K-chunk 32, cp.async 2-stage,
// 2 CTAs/SM for latency hiding.
// MODE 0: qkv = Wq @ x            (B k-major/trans, EPI split)   grid(16,24,4)
// MODE 1: M  += scale * V @ K^T   (B n-major,       EPI atomic)  grid(1, 4,32)
// MODE 2: C  = M @ Q              (B k-major/trans, EPI split)   grid(16,1,32)
// MODE 3: out = Wo @ C            (B k-major/trans, EPI fp32)    grid(16, 8,4)
// ---------------------------------------------------------------------------
template <int MODE>
__global__ __launch_bounds__(256, 2) void hgemm(float* __restrict__ OutExt) {
    constexpr bool BM0   = (MODE != 1);                     // B trans (k-major) path
    constexpr int  KLEN  = (MODE == 1) ? 512 : (MODE == 2 ? 128 : 1024);
    constexpr int  LDA   = (MODE == 1) ? SEQ : (MODE == 2 ? DH : CIN);
    constexpr int  LDB   = SEQ;
    constexpr int  LDY   = (MODE == 1) ? DH : SEQ;
    constexpr uint32_t AHI = 0, ALO = 10240, BHI = 20480;
    constexpr uint32_t BT  = BM0 ? 8704u : 10240u;          // B tile bytes
    constexpr uint32_t BLO = BHI + BT;
    constexpr uint32_t STAGE = BLO + BT;
    constexpr int NIT = KLEN / 32;

    extern __shared__ char smem[];
    const uint32_t sbase = smem_to_u32(smem);
    const int tid = threadIdx.x;
    const int lane = tid & 31, wid = tid >> 5;
    const int wm = wid & 1, wn = wid >> 1;
    const int z  = blockIdx.z;
    const int m0 = (MODE == 0 || MODE == 3) ? blockIdx.y * 128 : 0;
    const int n0 = blockIdx.x * 128;
    const int kStart = (MODE == 1) ? blockIdx.y * 512 : 0;

    const bf16 *Ahi_, *Alo_, *Bhi_, *Blo_;
    bf16 *Yhi_ = nullptr, *Ylo_ = nullptr;
    float* Yf_ = nullptr;
    if (MODE == 0) {
        Ahi_ = g_Wq_hi; Alo_ = g_Wq_lo;
        Bhi_ = g_x_hi + (size_t)z * CIN * SEQ; Blo_ = g_x_lo + (size_t)z * CIN * SEQ;
        Yhi_ = g_qkv_hi + (size_t)z * C3 * SEQ; Ylo_ = g_qkv_lo + (size_t)z * C3 * SEQ;
    } else if (MODE == 1) {
        int b = z >> 3, h = z & 7;
        size_t vo = ((size_t)b * C3 + 2 * CIN + h * DH) * SEQ;
        size_t ko = ((size_t)b * C3 + CIN + h * DH) * SEQ;
        Ahi_ = g_qkv_hi + vo; Alo_ = g_qkv_lo + vo;
        Bhi_ = g_qkv_hi + ko; Blo_ = g_qkv_lo + ko;
        Yf_  = g_M + (size_t)z * DH * DH;
    } else if (MODE == 2) {
        int b = z >> 3, h = z & 7;
        Ahi_ = g_M_hi + (size_t)z * DH * DH; Alo_ = g_M_lo + (size_t)z * DH * DH;
        size_t qo = ((size_t)b * C3 + h * DH) * SEQ;
        Bhi_ = g_qkv_hi + qo; Blo_ = g_qkv_lo + qo;
        size_t co = ((size_t)b * CIN + h * DH) * SEQ;
        Yhi_ = g_C_hi + co; Ylo_ = g_C_lo + co;
    } else {
        Ahi_ = g_Wo_hi; Alo_ = g_Wo_lo;
        Bhi_ = g_C_hi + (size_t)z * CIN * SEQ; Blo_ = g_C_lo + (size_t)z * CIN * SEQ;
        Yf_  = OutExt + (size_t)z * CIN * SEQ;
    }

    // ldmatrix base addresses (tile-relative)
    const uint32_t aAddr = (uint32_t)((wm * 64 + (lane & 15)) * 80 + (lane >> 4) * 16);
    uint32_t bAddr;
    if (BM0) {
        int seg = lane >> 3;
        bAddr = (uint32_t)(((seg & 1) * 8 + (lane & 7)) * 272 + (wn * 32 + (seg >> 1) * 8) * 2);
    } else {
        bAddr = (uint32_t)((wn * 32 + ((lane >> 4) << 3) + (lane & 7)) * 80 + ((lane >> 3) & 1) * 16);
    }

    float acc[4][4][4];
#pragma unroll
    for (int i = 0; i < 4; i++)
#pragma unroll
        for (int j = 0; j < 4; j++)
#pragma unroll
            for (int q = 0; q < 4; q++) acc[i][j][q] = 0.0f;

    auto fill = [&](int s) {
        const uint32_t sp = sbase + (uint32_t)((s & 1) * STAGE);
        const int k0 = kStart + s * 32;
#pragma unroll
        for (int t = 0; t < 2; t++) {
            int c = tid + t * 256;                 // 0..511
            int row = c >> 2, ke = (c & 3) * 8;
            size_t go = (size_t)(m0 + row) * LDA + k0 + ke;
            CP_ASYNC16(sp + AHI + (uint32_t)(row * 80 + ke * 2), Ahi_ + go);
            CP_ASYNC16(sp + ALO + (uint32_t)(row * 80 + ke * 2), Alo_ + go);
        }
        if (BM0) {
#pragma unroll
            for (int t = 0; t < 2; t++) {
                int c = tid + t * 256;
                int row = c >> 4, ne = (c & 15) * 8;
                size_t go = (size_t)(k0 + row) * LDB + n0 + ne;
                CP_ASYNC16(sp + BHI + (uint32_t)(row * 272 + ne * 2), Bhi_ + go);
                CP_ASYNC16(sp + BLO + (uint32_t)(row * 272 + ne * 2), Blo_ + go);
            }
        } else {
#pragma unroll
            for (int t = 0; t < 2; t++) {
                int c = tid + t * 256;
                int row = c >> 2, ke = (c & 3) * 8;
                size_t go = (size_t)(n0 + row) * LDB + k0 + ke;
                CP_ASYNC16(sp + BHI + (uint32_t)(row * 80 + ke * 2), Bhi_ + go);
                CP_ASYNC16(sp + BLO + (uint32_t)(row * 80 + ke * 2), Blo_ + go);
            }
        }
    };

    // prologue: 1 stage in flight
    fill(0); CP_COMMIT();

    for (int s = 0; s < NIT; s++) {
        if (s + 1 < NIT) {
            fill(s + 1); CP_COMMIT();
            CP_WAIT1();
        } else {
            CP_WAIT0();
        }
        __syncthreads();

        const uint32_t st = sbase + (uint32_t)((s & 1) * STAGE);
#pragma unroll
        for (int kk = 0; kk < 2; kk++) {
            uint32_t ah[4][4], al[4][4], bh[2][4], bl[2][4];
#pragma unroll
            for (int i = 0; i < 4; i++)
                LDSM_X4(ah[i], st + AHI + aAddr + (uint32_t)(i * (16 * 80) + kk * 32));
#pragma unroll
            for (int j2 = 0; j2 < 2; j2++) {
                if (BM0) LDSM_X4_T(bh[j2], st + BHI + bAddr + (uint32_t)(kk * (16 * 272) + j2 * 32));
                else     LDSM_X4  (bh[j2], st + BHI + bAddr + (uint32_t)(j2 * (16 * 80) + kk * 32));
            }
            // pass 1: hi*hi
#pragma unroll
            for (int i = 0; i < 4; i++)
#pragma unroll
                for (int j = 0; j < 4; j++)
                    MMA_BF16(acc[i][j], ah[i], bh[j >> 1][(j & 1) * 2], bh[j >> 1][(j & 1) * 2 + 1]);
            // pass 2: hi*lo
#pragma unroll
            for (int j2 = 0; j2 < 2; j2++) {
                if (BM0) LDSM_X4_T(bl[j2], st + BLO + bAddr + (uint32_t)(kk * (16 * 272) + j2 * 32));
                else     LDSM_X4  (bl[j2], st + BLO + bAddr + (uint32_t)(j2 * (16 * 80) + kk * 32));
            }
#pragma unroll
            for (int i = 0; i < 4; i++)
#pragma unroll
                for (int j = 0; j < 4; j++)
                    MMA_BF16(acc[i][j], ah[i], bl[j >> 1][(j & 1) * 2], bl[j >> 1][(j & 1) * 2 + 1]);
            // pass 3: lo*hi
#pragma unroll
            for (int i = 0; i < 4; i++)
                LDSM_X4(al[i], st + ALO + aAddr + (uint32_t)(i * (16 * 80) + kk * 32));
#pragma unroll
            for (int i = 0; i < 4; i++)
#pragma unroll
                for (int j = 0; j < 4; j++)
                    MMA_BF16(acc[i][j], al[i], bh[j >> 1][(j & 1) * 2], bh[j >> 1][(j & 1) * 2 + 1]);
        }
        __syncthreads();
    }

    // ---- epilogue ----
    const int g = lane >> 2, t4 = lane & 3;
#pragma unroll
    for (int i = 0; i < 4; i++) {
        int m = m0 + wm * 64 + i * 16 + g;
#pragma unroll
        for (int j = 0; j < 4; j++) {
            int n = n0 + wn * 32 + j * 8 + t4 * 2;
            if (MODE == 1) {
                int ml = m - m0;
                atomicAdd(&Yf_[(size_t)ml * LDY + n],       acc[i][j][0] * SCALE_F);
                atomicAdd(&Yf_[(size_t)ml * LDY + n + 1],   acc[i][j][1] * SCALE_F);
                atomicAdd(&Yf_[(size_t)(ml + 8) * LDY + n],     acc[i][j][2] * SCALE_F);
                atomicAdd(&Yf_[(size_t)(ml + 8) * LDY + n + 1], acc[i][j][3] * SCALE_F);
            } else if (MODE == 3) {
                *reinterpret_cast<float2*>(&Yf_[(size_t)m * LDY + n]) =
                    make_float2(acc[i][j][0], acc[i][j][1]);
                *reinterpret_cast<float2*>(&Yf_[(size_t)(m + 8) * LDY + n]) =
                    make_float2(acc[i][j][2], acc[i][j][3]);
            } else {
                // split store (hi/lo bf16)
#pragma unroll
                for (int half = 0; half < 2; half++) {
                    float v0 = acc[i][j][half * 2], v1 = acc[i][j][half * 2 + 1];
                    bf16 h0 = __float2bfloat16(v0), h1 = __float2bfloat16(v1);
                    size_t off = (size_t)(m + half * 8) * LDY + n;
                    *reinterpret_cast<__nv_bfloat162*>(&Yhi_[off]) = __nv_bfloat162(h0, h1);
                    *reinterpret_cast<__nv_bfloat162*>(&Ylo_[off]) =
                        __nv_bfloat162(__float2bfloat16(v0 - __bfloat162float(h0)),
                                       __float2bfloat16(v1 - __bfloat162float(h1)));
                }
            }
        }
    }
}

#define SMEM_BM0 (2 * 37888)   // 75776
#define SMEM_BM1 (2 * 40960)   // 81920

// ---------------------------------------------------------------------------
extern "C" void kernel_launch(void* const* d_in, const int* in_sizes, int n_in,
                              void* d_out, int out_size) {
    const float* x = nullptr;
    const float* W_qkv = nullptr;
    const float* W_out = nullptr;
    for (int i = 0; i < n_in; i++) {
        if (in_sizes[i] == BATCH * CIN * SEQ)      x     = (const float*)d_in[i];
        else if (in_sizes[i] == C3 * CIN)          W_qkv = (const float*)d_in[i];
        else if (in_sizes[i] == CIN * CIN)         W_out = (const float*)d_in[i];
    }
    float* out = (float*)d_out;

    cudaFuncSetAttribute(hgemm<0>, cudaFuncAttributeMaxDynamicSharedMemorySize, SMEM_BM0);
    cudaFuncSetAttribute(hgemm<1>, cudaFuncAttributeMaxDynamicSharedMemorySize, SMEM_BM1);
    cudaFuncSetAttribute(hgemm<2>, cudaFuncAttributeMaxDynamicSharedMemorySize, SMEM_BM0);
    cudaFuncSetAttribute(hgemm<3>, cudaFuncAttributeMaxDynamicSharedMemorySize, SMEM_BM0);

    // Symbol addresses for split kernels
    bf16 *pWqH, *pWqL, *pWoH, *pWoL, *pXH, *pXL, *pMH, *pML;
    float* pM;
    cudaGetSymbolAddress((void**)&pWqH, g_Wq_hi);
    cudaGetSymbolAddress((void**)&pWqL, g_Wq_lo);
    cudaGetSymbolAddress((void**)&pWoH, g_Wo_hi);
    cudaGetSymbolAddress((void**)&pWoL, g_Wo_lo);
    cudaGetSymbolAddress((void**)&pXH,  g_x_hi);
    cudaGetSymbolAddress((void**)&pXL,  g_x_lo);
    cudaGetSymbolAddress((void**)&pM,   g_M);
    cudaGetSymbolAddress((void**)&pMH,  g_M_hi);
    cudaGetSymbolAddress((void**)&pML,  g_M_lo);

    // Input splits
    split_pair<<<(C3 * CIN / 4 + 255) / 256, 256>>>(W_qkv, pWqH, pWqL, C3 * CIN / 4);
    split_pair<<<(CIN * CIN / 4 + 255) / 256, 256>>>(W_out, pWoH, pWoL, CIN * CIN / 4);
    split_pair<<<(BATCH * CIN * SEQ / 4 + 255) / 256, 256>>>(x, pXH, pXL, BATCH * CIN * SEQ / 4);

    // QKV projection
    hgemm<0><<<dim3(SEQ / 128, C3 / 128, BATCH), 256, SMEM_BM0>>>(nullptr);

    // Linear attention core: M = scale * V K^T, then C = M Q
    zero_M_kernel<<<512, 1024>>>();
    hgemm<1><<<dim3(1, 4, BATCH * NH), 256, SMEM_BM1>>>(nullptr);
    split_pair<<<(BATCH * NH * DH * DH / 4 + 255) / 256, 256>>>(pM, pMH, pML, BATCH * NH * DH * DH / 4);
    hgemm<2><<<dim3(SEQ / 128, 1, BATCH * NH), 256, SMEM_BM0>>>(nullptr);

    // Output projection
    hgemm<3><<<dim3(SEQ / 128, CIN / 128, BATCH), 256, SMEM_BM0>>>(out);
}

// round 9
// speedup vs baseline: 2.5545x; 1.0187x over previous
#include <cuda_runtime.h>
#include <cuda_bf16.h>
#include <cstdint>

// Problem constants
#define BATCH 4
#define SEQ   2048
#define CIN   1024
#define C3    3072
#define NH    8
#define DH    128
#define SCALE_F 0.08838834764831845f   // 1/sqrt(128)

typedef __nv_bfloat16 bf16;

// ---------------------------------------------------------------------------
// Scratch (device globals — no runtime allocation)
// ---------------------------------------------------------------------------
__device__ bf16 g_Wq_hi[(size_t)C3 * CIN];
__device__ bf16 g_Wq_lo[(size_t)C3 * CIN];
__device__ bf16 g_Wo_hi[(size_t)CIN * CIN];
__device__ bf16 g_Wo_lo[(size_t)CIN * CIN];
__device__ bf16 g_x_hi[(size_t)BATCH * CIN * SEQ];
__device__ bf16 g_x_lo[(size_t)BATCH * CIN * SEQ];
__device__ bf16 g_qkv_hi[(size_t)BATCH * C3 * SEQ];
__device__ bf16 g_qkv_lo[(size_t)BATCH * C3 * SEQ];
__device__ float g_M[(size_t)BATCH * NH * DH * DH];
__device__ bf16 g_M_hi[(size_t)BATCH * NH * DH * DH];
__device__ bf16 g_M_lo[(size_t)BATCH * NH * DH * DH];
__device__ bf16 g_C_hi[(size_t)BATCH * CIN * SEQ];
__device__ bf16 g_C_lo[(size_t)BATCH * CIN * SEQ];

// ---------------------------------------------------------------------------
// PTX helpers (sm_80-era features: legal in compute_103 PTX)
// ---------------------------------------------------------------------------
__device__ __forceinline__ uint32_t smem_to_u32(const void* p) {
    uint32_t a;
    asm("{ .reg .u64 t; cvta.to.shared.u64 t, %1; cvt.u32.u64 %0, t; }" : "=r"(a) : "l"(p));
    return a;
}
#define LDSM_X4(r, addr) \
    asm volatile("ldmatrix.sync.aligned.m8n8.x4.shared.b16 {%0,%1,%2,%3}, [%4];" \
                 : "=r"((r)[0]), "=r"((r)[1]), "=r"((r)[2]), "=r"((r)[3]) : "r"(addr))
#define LDSM_X4_T(r, addr) \
    asm volatile("ldmatrix.sync.aligned.m8n8.x4.trans.shared.b16 {%0,%1,%2,%3}, [%4];" \
                 : "=r"((r)[0]), "=r"((r)[1]), "=r"((r)[2]), "=r"((r)[3]) : "r"(addr))
#define MMA_BF16(c, a, b0, b1) \
    asm volatile("mma.sync.aligned.m16n8k16.row.col.f32.bf16.bf16.f32 " \
                 "{%0,%1,%2,%3},{%4,%5,%6,%7},{%8,%9},{%0,%1,%2,%3};" \
                 : "+f"((c)[0]), "+f"((c)[1]), "+f"((c)[2]), "+f"((c)[3]) \
                 : "r"((a)[0]), "r"((a)[1]), "r"((a)[2]), "r"((a)[3]), "r"(b0), "r"(b1))
#define CP_ASYNC16(dst, src) \
    asm volatile("cp.async.cg.shared.global [%0], [%1], 16;" :: "r"(dst), "l"(src) : "memory")
#define CP_COMMIT() asm volatile("cp.async.commit_group;" ::: "memory")
#define CP_WAIT1()  asm volatile("cp.async.wait_group 1;" ::: "memory")
#define CP_WAIT0()  asm volatile("cp.async.wait_group 0;" ::: "memory")

// ---------------------------------------------------------------------------
// fp32 -> bf16 hi + lo(residual) split, float4 vectorized
// ---------------------------------------------------------------------------
__global__ void split_pair(const float* __restrict__ src, bf16* __restrict__ hi,
                           bf16* __restrict__ lo, int n4) {
    int i = blockIdx.x * blockDim.x + threadIdx.x;
    if (i >= n4) return;
    float4 v = reinterpret_cast<const float4*>(src)[i];
    bf16 h0 = __float2bfloat16(v.x), h1 = __float2bfloat16(v.y);
    bf16 h2 = __float2bfloat16(v.z), h3 = __float2bfloat16(v.w);
    __nv_bfloat162* hp = reinterpret_cast<__nv_bfloat162*>(hi);
    __nv_bfloat162* lp = reinterpret_cast<__nv_bfloat162*>(lo);
    hp[2 * i]     = __nv_bfloat162(h0, h1);
    hp[2 * i + 1] = __nv_bfloat162(h2, h3);
    lp[2 * i]     = __nv_bfloat162(__float2bfloat16(v.x - __bfloat162float(h0)),
                                   __float2bfloat16(v.y - __bfloat162float(h1)));
    lp[2 * i + 1] = __nv_bfloat162(__float2bfloat16(v.z - __bfloat162float(h2)),
                                   __float2bfloat16(v.w - __bfloat162float(h3)));
}

__global__ void zero_M_kernel() {
    int i = blockIdx.x * blockDim.x + threadIdx.x;
    if (i < BATCH * NH * DH * DH) g_M[i] = 0.0f;
}

// ---------------------------------------------------------------------------
// Generic 3-pass bf16 HMMA GEMM, 128x128 tile, K-chunk 32, cp.async 2-stage,
// 2 CTAs/SM. Pass order (hi*hi, lo*hi, hi*lo) minimizes register live ranges
// so allocation lands <=120 regs (true 2-CTA residency; 127 regs is an
// exact-fit 65536 and the HW refuses the 2nd CTA).
// MODE 0: qkv = Wq @ x            (B k-major/trans, EPI split)   grid(16,24,4)
// MODE 1: M  += scale * V @ K^T   (B n-major,       EPI atomic)  grid(1, 8,32)
// MODE 2: C  = M @ Q              (B k-major/trans, EPI split)   grid(16,1,32)
// MODE 3: out = Wo @ C            (B k-major/trans, EPI fp32)    grid(16, 8,4)
// ---------------------------------------------------------------------------
template <int MODE>
__global__ __launch_bounds__(256, 2) void hgemm(float* __restrict__ OutExt) {
    constexpr bool BM0   = (MODE != 1);                     // B trans (k-major) path
    constexpr int  KLEN  = (MODE == 1) ? 256 : (MODE == 2 ? 128 : 1024);
    constexpr int  LDA   = (MODE == 1) ? SEQ : (MODE == 2 ? DH : CIN);
    constexpr int  LDB   = SEQ;
    constexpr int  LDY   = (MODE == 1) ? DH : SEQ;
    constexpr uint32_t AHI = 0, ALO = 10240, BHI = 20480;
    constexpr uint32_t BT  = BM0 ? 8704u : 10240u;          // B tile bytes
    constexpr uint32_t BLO = BHI + BT;
    constexpr uint32_t STAGE = BLO + BT;
    constexpr int NIT = KLEN / 32;

    extern __shared__ char smem[];
    const uint32_t sbase = smem_to_u32(smem);
    const int tid = threadIdx.x;
    const int lane = tid & 31, wid = tid >> 5;
    const int wm = wid & 1, wn = wid >> 1;
    const int z  = blockIdx.z;
    const int m0 = (MODE == 0 || MODE == 3) ? blockIdx.y * 128 : 0;
    const int n0 = blockIdx.x * 128;
    const int kStart = (MODE == 1) ? blockIdx.y * 256 : 0;

    const bf16 *Ahi_, *Alo_, *Bhi_, *Blo_;
    bf16 *Yhi_ = nullptr, *Ylo_ = nullptr;
    float* Yf_ = nullptr;
    if (MODE == 0) {
        Ahi_ = g_Wq_hi; Alo_ = g_Wq_lo;
        Bhi_ = g_x_hi + (size_t)z * CIN * SEQ; Blo_ = g_x_lo + (size_t)z * CIN * SEQ;
        Yhi_ = g_qkv_hi + (size_t)z * C3 * SEQ; Ylo_ = g_qkv_lo + (size_t)z * C3 * SEQ;
    } else if (MODE == 1) {
        int b = z >> 3, h = z & 7;
        size_t vo = ((size_t)b * C3 + 2 * CIN + h * DH) * SEQ;
        size_t ko = ((size_t)b * C3 + CIN + h * DH) * SEQ;
        Ahi_ = g_qkv_hi + vo; Alo_ = g_qkv_lo + vo;
        Bhi_ = g_qkv_hi + ko; Blo_ = g_qkv_lo + ko;
        Yf_  = g_M + (size_t)z * DH * DH;
    } else if (MODE == 2) {
        int b = z >> 3, h = z & 7;
        Ahi_ = g_M_hi + (size_t)z * DH * DH; Alo_ = g_M_lo + (size_t)z * DH * DH;
        size_t qo = ((size_t)b * C3 + h * DH) * SEQ;
        Bhi_ = g_qkv_hi + qo; Blo_ = g_qkv_lo + qo;
        size_t co = ((size_t)b * CIN + h * DH) * SEQ;
        Yhi_ = g_C_hi + co; Ylo_ = g_C_lo + co;
    } else {
        Ahi_ = g_Wo_hi; Alo_ = g_Wo_lo;
        Bhi_ = g_C_hi + (size_t)z * CIN * SEQ; Blo_ = g_C_lo + (size_t)z * CIN * SEQ;
        Yf_  = OutExt + (size_t)z * CIN * SEQ;
    }

    // ldmatrix base addresses (tile-relative)
    const uint32_t aAddr = (uint32_t)((wm * 64 + (lane & 15)) * 80 + (lane >> 4) * 16);
    uint32_t bAddr;
    if (BM0) {
        int seg = lane >> 3;
        bAddr = (uint32_t)(((seg & 1) * 8 + (lane & 7)) * 272 + (wn * 32 + (seg >> 1) * 8) * 2);
    } else {
        bAddr = (uint32_t)((wn * 32 + ((lane >> 4) << 3) + (lane & 7)) * 80 + ((lane >> 3) & 1) * 16);
    }

    float acc[4][4][4];
#pragma unroll
    for (int i = 0; i < 4; i++)
#pragma unroll
        for (int j = 0; j < 4; j++)
#pragma unroll
            for (int q = 0; q < 4; q++) acc[i][j][q] = 0.0f;

    auto fill = [&](int s) {
        const uint32_t sp = sbase + (uint32_t)((s & 1) * STAGE);
        const int k0 = kStart + s * 32;
#pragma unroll
        for (int t = 0; t < 2; t++) {
            int c = tid + t * 256;                 // 0..511
            int row = c >> 2, ke = (c & 3) * 8;
            size_t go = (size_t)(m0 + row) * LDA + k0 + ke;
            CP_ASYNC16(sp + AHI + (uint32_t)(row * 80 + ke * 2), Ahi_ + go);
            CP_ASYNC16(sp + ALO + (uint32_t)(row * 80 + ke * 2), Alo_ + go);
        }
        if (BM0) {
#pragma unroll
            for (int t = 0; t < 2; t++) {
                int c = tid + t * 256;
                int row = c >> 4, ne = (c & 15) * 8;
                size_t go = (size_t)(k0 + row) * LDB + n0 + ne;
                CP_ASYNC16(sp + BHI + (uint32_t)(row * 272 + ne * 2), Bhi_ + go);
                CP_ASYNC16(sp + BLO + (uint32_t)(row * 272 + ne * 2), Blo_ + go);
            }
        } else {
#pragma unroll
            for (int t = 0; t < 2; t++) {
                int c = tid + t * 256;
                int row = c >> 2, ke = (c & 3) * 8;
                size_t go = (size_t)(n0 + row) * LDB + k0 + ke;
                CP_ASYNC16(sp + BHI + (uint32_t)(row * 80 + ke * 2), Bhi_ + go);
                CP_ASYNC16(sp + BLO + (uint32_t)(row * 80 + ke * 2), Blo_ + go);
            }
        }
    };

    // prologue: 1 stage in flight
    fill(0); CP_COMMIT();

    for (int s = 0; s < NIT; s++) {
        if (s + 1 < NIT) {
            fill(s + 1); CP_COMMIT();
            CP_WAIT1();
        } else {
            CP_WAIT0();
        }
        __syncthreads();

        const uint32_t st = sbase + (uint32_t)((s & 1) * STAGE);
#pragma unroll
        for (int kk = 0; kk < 2; kk++) {
            uint32_t ah[4][4], bh[2][4];
#pragma unroll
            for (int i = 0; i < 4; i++)
                LDSM_X4(ah[i], st + AHI + aAddr + (uint32_t)(i * (16 * 80) + kk * 32));
#pragma unroll
            for (int j2 = 0; j2 < 2; j2++) {
                if (BM0) LDSM_X4_T(bh[j2], st + BHI + bAddr + (uint32_t)(kk * (16 * 272) + j2 * 32));
                else     LDSM_X4  (bh[j2], st + BHI + bAddr + (uint32_t)(j2 * (16 * 80) + kk * 32));
            }
            // pass 1: hi*hi
#pragma unroll
            for (int i = 0; i < 4; i++)
#pragma unroll
                for (int j = 0; j < 4; j++)
                    MMA_BF16(acc[i][j], ah[i], bh[j >> 1][(j & 1) * 2], bh[j >> 1][(j & 1) * 2 + 1]);
            // pass 2: lo*hi  (al live range: this block only; bh dies here)
            {
                uint32_t al[4][4];
#pragma unroll
                for (int i = 0; i < 4; i++)
                    LDSM_X4(al[i], st + ALO + aAddr + (uint32_t)(i * (16 * 80) + kk * 32));
#pragma unroll
                for (int i = 0; i < 4; i++)
#pragma unroll
                    for (int j = 0; j < 4; j++)
                        MMA_BF16(acc[i][j], al[i], bh[j >> 1][(j & 1) * 2], bh[j >> 1][(j & 1) * 2 + 1]);
            }
            // pass 3: hi*lo  (bl reuses bh's register budget)
            {
                uint32_t bl[2][4];
#pragma unroll
                for (int j2 = 0; j2 < 2; j2++) {
                    if (BM0) LDSM_X4_T(bl[j2], st + BLO + bAddr + (uint32_t)(kk * (16 * 272) + j2 * 32));
                    else     LDSM_X4  (bl[j2], st + BLO + bAddr + (uint32_t)(j2 * (16 * 80) + kk * 32));
                }
#pragma unroll
                for (int i = 0; i < 4; i++)
#pragma unroll
                    for (int j = 0; j < 4; j++)
                        MMA_BF16(acc[i][j], ah[i], bl[j >> 1][(j & 1) * 2], bl[j >> 1][(j & 1) * 2 + 1]);
            }
        }
        __syncthreads();
    }

    // ---- epilogue ----
    const int g = lane >> 2, t4 = lane & 3;
#pragma unroll
    for (int i = 0; i < 4; i++) {
        int m = m0 + wm * 64 + i * 16 + g;
#pragma unroll
        for (int j = 0; j < 4; j++) {
            int n = n0 + wn * 32 + j * 8 + t4 * 2;
            if (MODE == 1) {
                int ml = m - m0;
                atomicAdd(&Yf_[(size_t)ml * LDY + n],       acc[i][j][0] * SCALE_F);
                atomicAdd(&Yf_[(size_t)ml * LDY + n + 1],   acc[i][j][1] * SCALE_F);
                atomicAdd(&Yf_[(size_t)(ml + 8) * LDY + n],     acc[i][j][2] * SCALE_F);
                atomicAdd(&Yf_[(size_t)(ml + 8) * LDY + n + 1], acc[i][j][3] * SCALE_F);
            } else if (MODE == 3) {
                *reinterpret_cast<float2*>(&Yf_[(size_t)m * LDY + n]) =
                    make_float2(acc[i][j][0], acc[i][j][1]);
                *reinterpret_cast<float2*>(&Yf_[(size_t)(m + 8) * LDY + n]) =
                    make_float2(acc[i][j][2], acc[i][j][3]);
            } else {
                // split store (hi/lo bf16)
#pragma unroll
                for (int half = 0; half < 2; half++) {
                    float v0 = acc[i][j][half * 2], v1 = acc[i][j][half * 2 + 1];
                    bf16 h0 = __float2bfloat16(v0), h1 = __float2bfloat16(v1);
                    size_t off = (size_t)(m + half * 8) * LDY + n;
                    *reinterpret_cast<__nv_bfloat162*>(&Yhi_[off]) = __nv_bfloat162(h0, h1);
                    *reinterpret_cast<__nv_bfloat162*>(&Ylo_[off]) =
                        __nv_bfloat162(__float2bfloat16(v0 - __bfloat162float(h0)),
                                       __float2bfloat16(v1 - __bfloat162float(h1)));
                }
            }
        }
    }
}

#define SMEM_BM0 (2 * 37888)   // 75776
#define SMEM_BM1 (2 * 40960)   // 81920

// ---------------------------------------------------------------------------
extern "C" void kernel_launch(void* const* d_in, const int* in_sizes, int n_in,
                              void* d_out, int out_size) {
    const float* x = nullptr;
    const float* W_qkv = nullptr;
    const float* W_out = nullptr;
    for (int i = 0; i < n_in; i++) {
        if (in_sizes[i] == BATCH * CIN * SEQ)      x     = (const float*)d_in[i];
        else if (in_sizes[i] == C3 * CIN)          W_qkv = (const float*)d_in[i];
        else if (in_sizes[i] == CIN * CIN)         W_out = (const float*)d_in[i];
    }
    float* out = (float*)d_out;

    cudaFuncSetAttribute(hgemm<0>, cudaFuncAttributeMaxDynamicSharedMemorySize, SMEM_BM0);
    cudaFuncSetAttribute(hgemm<1>, cudaFuncAttributeMaxDynamicSharedMemorySize, SMEM_BM1);
    cudaFuncSetAttribute(hgemm<2>, cudaFuncAttributeMaxDynamicSharedMemorySize, SMEM_BM0);
    cudaFuncSetAttribute(hgemm<3>, cudaFuncAttributeMaxDynamicSharedMemorySize, SMEM_BM0);
    cudaFuncSetAttribute(hgemm<0>, cudaFuncAttributePreferredSharedMemoryCarveout, cudaSharedmemCarveoutMaxShared);
    cudaFuncSetAttribute(hgemm<1>, cudaFuncAttributePreferredSharedMemoryCarveout, cudaSharedmemCarveoutMaxShared);
    cudaFuncSetAttribute(hgemm<2>, cudaFuncAttributePreferredSharedMemoryCarveout, cudaSharedmemCarveoutMaxShared);
    cudaFuncSetAttribute(hgemm<3>, cudaFuncAttributePreferredSharedMemoryCarveout, cudaSharedmemCarveoutMaxShared);

    // Symbol addresses for split kernels
    bf16 *pWqH, *pWqL, *pWoH, *pWoL, *pXH, *pXL, *pMH, *pML;
    float* pM;
    cudaGetSymbolAddress((void**)&pWqH, g_Wq_hi);
    cudaGetSymbolAddress((void**)&pWqL, g_Wq_lo);
    cudaGetSymbolAddress((void**)&pWoH, g_Wo_hi);
    cudaGetSymbolAddress((void**)&pWoL, g_Wo_lo);
    cudaGetSymbolAddress((void**)&pXH,  g_x_hi);
    cudaGetSymbolAddress((void**)&pXL,  g_x_lo);
    cudaGetSymbolAddress((void**)&pM,   g_M);
    cudaGetSymbolAddress((void**)&pMH,  g_M_hi);
    cudaGetSymbolAddress((void**)&pML,  g_M_lo);

    // Input splits
    split_pair<<<(C3 * CIN / 4 + 255) / 256, 256>>>(W_qkv, pWqH, pWqL, C3 * CIN / 4);
    split_pair<<<(CIN * CIN / 4 + 255) / 256, 256>>>(W_out, pWoH, pWoL, CIN * CIN / 4);
    split_pair<<<(BATCH * CIN * SEQ / 4 + 255) / 256, 256>>>(x, pXH, pXL, BATCH * CIN * SEQ / 4);

    // QKV projection
    hgemm<0><<<dim3(SEQ / 128, C3 / 128, BATCH), 256, SMEM_BM0>>>(nullptr);

    // Linear attention core: M = scale * V K^T, then C = M Q
    zero_M_kernel<<<512, 1024>>>();
    hgemm<1><<<dim3(1, 8, BATCH * NH), 256, SMEM_BM1>>>(nullptr);
    split_pair<<<(BATCH * NH * DH * DH / 4 + 255) / 256, 256>>>(pM, pMH, pML, BATCH * NH * DH * DH / 4);
    hgemm<2><<<dim3(SEQ / 128, 1, BATCH * NH), 256, SMEM_BM0>>>(nullptr);

    // Output projection
    hgemm<3><<<dim3(SEQ / 128, CIN / 128, BATCH), 256, SMEM_BM0>>>(out);
}